// round 2
// baseline (speedup 1.0000x reference)
#include <cuda_runtime.h>

// Problem constants
#define NN    25000
#define NPAD  25024          // multiple of 32
#define EE    400000
#define FN    32
#define FE    16
#define HH    16
#define MM    16
#define MPITERS 3

// ---------------- scratch (device globals; no allocation allowed) ----------
__device__ float g_hidden [NPAD * HH];
__device__ float g_hidden0[NPAD * HH];
__device__ float g_T      [NPAD * FE * MM];   // T[n][f*16+m]
__device__ float g_bb     [NPAD * MM];
__device__ float g_msg    [NPAD * MM];
// CSR-by-sender scratch
__device__ int   g_count  [NPAD];
__device__ int   g_cursor [NPAD];
__device__ int   g_perm   [EE];
__device__ float g_efs    [(long)EE * FE];    // edge features sorted by sender
__device__ int   g_recvs  [EE];
__device__ int   g_sends  [EE];

// ---------------- f32x2 helpers -------------------------------------------
__device__ __forceinline__ unsigned long long pk2(float lo, float hi) {
    unsigned long long d;
    asm("mov.b64 %0, {%1, %2};" : "=l"(d) : "r"(__float_as_uint(lo)), "r"(__float_as_uint(hi)));
    return d;
}
__device__ __forceinline__ unsigned long long fma2(unsigned long long a,
                                                   unsigned long long b,
                                                   unsigned long long c) {
    unsigned long long d;
    asm("fma.rn.f32x2 %0, %1, %2, %3;" : "=l"(d) : "l"(a), "l"(b), "l"(c));
    return d;
}
__device__ __forceinline__ float upk_sum(unsigned long long v) {
    unsigned int a, b;
    asm("mov.b64 {%0, %1}, %2;" : "=r"(a), "=r"(b) : "l"(v));
    return __uint_as_float(a) + __uint_as_float(b);
}
__device__ __forceinline__ void upk(unsigned long long v, float& a, float& b) {
    unsigned int x, y;
    asm("mov.b64 {%0, %1}, %2;" : "=r"(x), "=r"(y) : "l"(v));
    a = __uint_as_float(x); b = __uint_as_float(y);
}
__device__ __forceinline__ float dot4(float4 a, float4 b) {
    float r = a.x * b.x;
    r = fmaf(a.y, b.y, r);
    r = fmaf(a.z, b.z, r);
    r = fmaf(a.w, b.w, r);
    return r;
}

// ---------------- kernel 1: init hidden + zero counters --------------------
__global__ __launch_bounds__(256)
void init_kernel(const float* __restrict__ nf, const float* __restrict__ Wi,
                 const float* __restrict__ bi) {
    __shared__ float Wsh[FN * HH];
    int tid = threadIdx.x;
    int gid = blockIdx.x * 256 + tid;
    if (gid < NPAD) g_count[gid] = 0;

    int j  = tid & 15;
    int nl = tid >> 4;
    int n  = blockIdx.x * 16 + nl;
    for (int idx = tid; idx < FN * HH; idx += 256) Wsh[idx] = Wi[idx];
    __syncthreads();
    if (n >= NPAD) return;
    int nr = (n < NN) ? n : (NN - 1);
    const float* row = nf + (long)nr * FN;
    float acc = bi[j];
#pragma unroll
    for (int f = 0; f < FN; f++) acc = fmaf(row[f], Wsh[f * 16 + j], acc);
    g_hidden [n * 16 + j] = acc;
    g_hidden0[n * 16 + j] = acc;
}

// ---------------- CSR build: histogram, scan, scatter, gather --------------
__global__ __launch_bounds__(256)
void hist_kernel(const int* __restrict__ send) {
    int e = blockIdx.x * 256 + threadIdx.x;
    if (e < EE) atomicAdd(&g_count[send[e]], 1);
}

__global__ __launch_bounds__(1024)
void scan_kernel() {
    __shared__ int sh[1024];
    int t = threadIdx.x;
    int vals[25];
    int sum = 0;
    int base = t * 25;
#pragma unroll
    for (int k = 0; k < 25; k++) {
        int idx = base + k;
        int v = (idx < NPAD) ? g_count[idx] : 0;
        vals[k] = v; sum += v;
    }
    sh[t] = sum;
    __syncthreads();
    for (int off = 1; off < 1024; off <<= 1) {
        int v = (t >= off) ? sh[t - off] : 0;
        __syncthreads();
        sh[t] += v;
        __syncthreads();
    }
    int ex = (t == 0) ? 0 : sh[t - 1];
#pragma unroll
    for (int k = 0; k < 25; k++) {
        int idx = base + k;
        if (idx < NPAD) { g_cursor[idx] = ex; ex += vals[k]; }
    }
}

__global__ __launch_bounds__(256)
void scatter_kernel(const int* __restrict__ send) {
    int e = blockIdx.x * 256 + threadIdx.x;
    if (e < EE) {
        int s = send[e];
        int p = atomicAdd(&g_cursor[s], 1);
        g_perm[p] = e;
    }
}

__global__ __launch_bounds__(256)
void gather_kernel(const float* __restrict__ ef, const int* __restrict__ recv,
                   const int* __restrict__ send) {
    int gid = blockIdx.x * 256 + threadIdx.x;
    int i = gid >> 2, q = gid & 3;
    if (i >= EE) return;
    int e = g_perm[i];
    ((float4*)(g_efs + (long)i * 16))[q] = ((const float4*)(ef + (long)e * 16))[q];
    if (q == 0) { g_recvs[i] = recv[e]; g_sends[i] = send[e]; }
}

// ---------------- kernel 2: per-node T / bb  (+ zero msg fused) ------------
__global__ __launch_bounds__(256)
void t_kernel(const float* __restrict__ We, const float* __restrict__ be) {
    // zero g_msg (independent buffer; no sync needed before T work)
    for (int idx = blockIdx.x * 256 + threadIdx.x; idx < NPAD * MM;
         idx += gridDim.x * 256)
        g_msg[idx] = 0.f;

    __shared__ __align__(16) float sh[64 * HH];
    int tid = threadIdx.x;
    int f = tid >> 4;
    int m = tid & 15;

    const float4* wp = (const float4*)(We + (f * 256 + m * 16));
    float4 w0 = wp[0], w1 = wp[1], w2 = wp[2], w3 = wp[3];

    float4 b0 = make_float4(0, 0, 0, 0), b1 = b0, b2 = b0, b3 = b0;
    if (f == 0) {
        const float4* bp = (const float4*)(be + m * 16);
        b0 = bp[0]; b1 = bp[1]; b2 = bp[2]; b3 = bp[3];
    }

    int base = blockIdx.x * 64;
    int cnt = NN - base;
    if (cnt > 64) cnt = 64;
    if (cnt <= 0) return;

    for (int idx = tid; idx < cnt * HH; idx += 256)
        sh[idx] = g_hidden[base * HH + idx];
    __syncthreads();

#pragma unroll 2
    for (int nl = 0; nl < cnt; nl++) {
        const float4* hp = (const float4*)(sh + nl * HH);
        float4 h0 = hp[0], h1 = hp[1], h2 = hp[2], h3 = hp[3];
        float acc = dot4(w0, h0) + dot4(w1, h1) + dot4(w2, h2) + dot4(w3, h3);
        g_T[(long)(base + nl) * 256 + tid] = acc;
        if (f == 0) {
            float bacc = dot4(b0, h0) + dot4(b1, h1) + dot4(b2, h2) + dot4(b3, h3);
            g_bb[(base + nl) * 16 + m] = bacc;
        }
    }
}

// ---------------- kernel 3: per-edge message (sorted) + vector red ---------
// 4 threads per sorted edge; mg owns m = mg*4 .. mg*4+3. T rows hit L1 due to
// sender-sorted locality.
__global__ __launch_bounds__(256)
void edge_kernel() {
    int tid = threadIdx.x;
    int i  = blockIdx.x * 64 + (tid >> 2);
    int mg = tid & 3;

    int s = g_sends[i];
    const float* efr = g_efs + (long)i * 16;
    float4 e0 = ((const float4*)efr)[0];
    float4 e1 = ((const float4*)efr)[1];
    float4 e2 = ((const float4*)efr)[2];
    float4 e3 = ((const float4*)efr)[3];

    float4 bbv = *(const float4*)(g_bb + s * 16 + mg * 4);
    unsigned long long accL = pk2(bbv.x, bbv.y);
    unsigned long long accH = pk2(bbv.z, bbv.w);

    const ulonglong2* Tb = (const ulonglong2*)(g_T + (long)s * 256) + mg;

#define ESTEP(F, W) { ulonglong2 tv = Tb[(F) * 4];                  \
        unsigned long long ww = pk2((W), (W));                      \
        accL = fma2(tv.x, ww, accL); accH = fma2(tv.y, ww, accH); }
    ESTEP(0,  e0.x) ESTEP(1,  e0.y) ESTEP(2,  e0.z) ESTEP(3,  e0.w)
    ESTEP(4,  e1.x) ESTEP(5,  e1.y) ESTEP(6,  e1.z) ESTEP(7,  e1.w)
    ESTEP(8,  e2.x) ESTEP(9,  e2.y) ESTEP(10, e2.z) ESTEP(11, e2.w)
    ESTEP(12, e3.x) ESTEP(13, e3.y) ESTEP(14, e3.z) ESTEP(15, e3.w)
#undef ESTEP

    float r0, r1, r2, r3;
    upk(accL, r0, r1);
    upk(accH, r2, r3);
    float* dst = g_msg + g_recvs[i] * 16 + mg * 4;
    asm volatile("red.global.add.v4.f32 [%0], {%1, %2, %3, %4};"
                 :: "l"(dst), "f"(r0), "f"(r1), "f"(r2), "f"(r3) : "memory");
}

// ---------------- kernel 4: GRU, 2 nodes per thread (ILP) ------------------
__global__ __launch_bounds__(256)
void gru_kernel(const float* __restrict__ Wi, const float* __restrict__ Wh,
                const float* __restrict__ bi, const float* __restrict__ bh) {
    __shared__ __align__(16) float sh_h[2][32][16];
    __shared__ float sh_seq[32][32];

    int tid = threadIdx.x;
    int j  = tid & 15;
    int sl = tid >> 4;                 // 0..15
    int nA = blockIdx.x * 32 + sl;
    int nB = nA + 16;

    unsigned long long wz[8], wr[8], wh[8];
#pragma unroll
    for (int k = 0; k < 8; k++) {
        wz[k] = pk2(Wh[(2 * k) * 48 + j],      Wh[(2 * k + 1) * 48 + j]);
        wr[k] = pk2(Wh[(2 * k) * 48 + 16 + j], Wh[(2 * k + 1) * 48 + 16 + j]);
        wh[k] = pk2(Wh[(2 * k) * 48 + 32 + j], Wh[(2 * k + 1) * 48 + 32 + j]);
    }
    float wiz = Wi[j], wir = Wi[16 + j], wih = Wi[32 + j];
    float biz = bi[j], bir = bi[16 + j], bih = bi[32 + j];
    float bhz = bh[j], bhr = bh[16 + j], bhh = bh[32 + j];

    sh_seq[sl][j]           = g_hidden[nA * 16 + j];
    sh_seq[sl][16 + j]      = g_msg   [nA * 16 + j];
    sh_seq[sl + 16][j]      = g_hidden[nB * 16 + j];
    sh_seq[sl + 16][16 + j] = g_msg   [nB * 16 + j];
    sh_h[0][sl][j] = 0.f;
    sh_h[0][sl + 16][j] = 0.f;
    float hA = 0.f, hB = 0.f;
    __syncthreads();

#pragma unroll 1
    for (int t = 0; t < 32; t++) {
        int cur = t & 1;
        float xA = sh_seq[sl][t];
        float xB = sh_seq[sl + 16][t];
        const ulonglong2* hpA = (const ulonglong2*)sh_h[cur][sl];
        const ulonglong2* hpB = (const ulonglong2*)sh_h[cur][sl + 16];
        unsigned long long azA = pk2(bhz, 0.f), arA = pk2(bhr, 0.f), ahA = pk2(bhh, 0.f);
        unsigned long long azB = pk2(bhz, 0.f), arB = pk2(bhr, 0.f), ahB = pk2(bhh, 0.f);
#pragma unroll
        for (int k = 0; k < 4; k++) {
            ulonglong2 pA = hpA[k];
            ulonglong2 pB = hpB[k];
            azA = fma2(pA.x, wz[2 * k],     azA);
            azA = fma2(pA.y, wz[2 * k + 1], azA);
            arA = fma2(pA.x, wr[2 * k],     arA);
            arA = fma2(pA.y, wr[2 * k + 1], arA);
            ahA = fma2(pA.x, wh[2 * k],     ahA);
            ahA = fma2(pA.y, wh[2 * k + 1], ahA);
            azB = fma2(pB.x, wz[2 * k],     azB);
            azB = fma2(pB.y, wz[2 * k + 1], azB);
            arB = fma2(pB.x, wr[2 * k],     arB);
            arB = fma2(pB.y, wr[2 * k + 1], arB);
            ahB = fma2(pB.x, wh[2 * k],     ahB);
            ahB = fma2(pB.y, wh[2 * k + 1], ahB);
        }
        // node A gates
        {
            float ghz = upk_sum(azA), ghr = upk_sum(arA), ghh = upk_sum(ahA);
            float gz = fmaf(xA, wiz, biz) + ghz;
            float gr = fmaf(xA, wir, bir) + ghr;
            float z = 1.f / (1.f + __expf(-gz));
            float r = 1.f / (1.f + __expf(-gr));
            float ga = fmaf(xA, wih, bih) + r * ghh;
            float hc = 2.f / (1.f + __expf(-2.f * ga)) - 1.f;
            hA = hc + z * (hA - hc);
        }
        // node B gates
        {
            float ghz = upk_sum(azB), ghr = upk_sum(arB), ghh = upk_sum(ahB);
            float gz = fmaf(xB, wiz, biz) + ghz;
            float gr = fmaf(xB, wir, bir) + ghr;
            float z = 1.f / (1.f + __expf(-gz));
            float r = 1.f / (1.f + __expf(-gr));
            float ga = fmaf(xB, wih, bih) + r * ghh;
            float hc = 2.f / (1.f + __expf(-2.f * ga)) - 1.f;
            hB = hc + z * (hB - hc);
        }
        sh_h[cur ^ 1][sl][j] = hA;
        sh_h[cur ^ 1][sl + 16][j] = hB;
        __syncwarp();
    }
    g_hidden[nA * 16 + j] = hA;
    g_hidden[nB * 16 + j] = hB;
}

// ---------------- readout --------------------------------------------------
__global__ void zero_out_kernel(float* out) { out[0] = 0.f; }

__global__ __launch_bounds__(256)
void readout_kernel(const float* __restrict__ Wri, const float* __restrict__ bri,
                    const float* __restrict__ Wrj, const float* __restrict__ brj,
                    float* __restrict__ out) {
    int n = blockIdx.x * 256 + threadIdx.x;
    float p = 0.f;
    if (n < NN) {
        const float4* hp  = (const float4*)(g_hidden  + n * 16);
        const float4* h0p = (const float4*)(g_hidden0 + n * 16);
        const float4* wi  = (const float4*)Wri;
        const float4* wj  = (const float4*)Wrj;
        float4 h0 = hp[0], h1 = hp[1], h2 = hp[2], h3 = hp[3];
        float4 g0 = h0p[0], g1 = h0p[1], g2 = h0p[2], g3 = h0p[3];
        float iv = bri[0]
                 + dot4(h0, wi[0]) + dot4(h1, wi[1]) + dot4(h2, wi[2]) + dot4(h3, wi[3])
                 + dot4(g0, wi[4]) + dot4(g1, wi[5]) + dot4(g2, wi[6]) + dot4(g3, wi[7]);
        float jv = brj[0]
                 + dot4(h0, wj[0]) + dot4(h1, wj[1]) + dot4(h2, wj[2]) + dot4(h3, wj[3]);
        p = iv * jv;
    }
#pragma unroll
    for (int off = 16; off > 0; off >>= 1)
        p += __shfl_down_sync(0xffffffffu, p, off);
    if ((threadIdx.x & 31) == 0) atomicAdd(out, p);
}

// ---------------- launch ---------------------------------------------------
extern "C" void kernel_launch(void* const* d_in, const int* in_sizes, int n_in,
                              void* d_out, int out_size) {
    const float* nf     = (const float*)d_in[0];
    const float* ef     = (const float*)d_in[1];
    const float* W_init = (const float*)d_in[2];
    const float* b_init = (const float*)d_in[3];
    const float* W_edge = (const float*)d_in[4];
    const float* b_edge = (const float*)d_in[5];
    const float* Wi_gru = (const float*)d_in[6];
    const float* Wh_gru = (const float*)d_in[7];
    const float* bi_gru = (const float*)d_in[8];
    const float* bh_gru = (const float*)d_in[9];
    const float* W_ri   = (const float*)d_in[10];
    const float* b_ri   = (const float*)d_in[11];
    const float* W_rj   = (const float*)d_in[12];
    const float* b_rj   = (const float*)d_in[13];
    const int*   recv   = (const int*)d_in[14];
    const int*   send   = (const int*)d_in[15];
    float* out = (float*)d_out;

    init_kernel<<<NPAD / 16, 256>>>(nf, W_init, b_init);
    hist_kernel<<<(EE + 255) / 256, 256>>>(send);
    scan_kernel<<<1, 1024>>>();
    scatter_kernel<<<(EE + 255) / 256, 256>>>(send);
    gather_kernel<<<EE * 4 / 256, 256>>>(ef, recv, send);

    for (int it = 0; it < MPITERS; it++) {
        t_kernel<<<(NN + 63) / 64, 256>>>(W_edge, b_edge);
        edge_kernel<<<EE / 64, 256>>>();
        gru_kernel<<<NPAD / 32, 256>>>(Wi_gru, Wh_gru, bi_gru, bh_gru);
    }

    zero_out_kernel<<<1, 1>>>(out);
    readout_kernel<<<(NN + 255) / 256, 256>>>(W_ri, b_ri, W_rj, b_rj, out);
}

// round 3
// speedup vs baseline: 1.3265x; 1.3265x over previous
#include <cuda_runtime.h>

// Problem constants
#define NN    25000
#define NPAD  25024          // multiple of 32
#define EE    400000
#define FN    32
#define FE    16
#define HH    16
#define MM    16
#define MPITERS 3

// ---------------- scratch (device globals; no allocation allowed) ----------
__device__ float g_hidden [NPAD * HH];
__device__ float g_hidden0[NPAD * HH];
__device__ float g_T      [NPAD * FE * MM];   // T[n][f*16+m]
__device__ float g_bb     [NPAD * MM];
__device__ float g_msg    [NPAD * MM];
// CSR-by-sender scratch
__device__ int   g_count  [NPAD];
__device__ int   g_cursor [NPAD];
__device__ int   g_perm   [EE];               // sorted-pos -> original edge id
__device__ int   g_recvs  [EE];               // receiver, sender-sorted order
__device__ int   g_sends  [EE];               // sender, sorted (non-decreasing)

// ---------------- f32x2 helpers -------------------------------------------
__device__ __forceinline__ unsigned long long pk2(float lo, float hi) {
    unsigned long long d;
    asm("mov.b64 %0, {%1, %2};" : "=l"(d) : "r"(__float_as_uint(lo)), "r"(__float_as_uint(hi)));
    return d;
}
__device__ __forceinline__ unsigned long long fma2(unsigned long long a,
                                                   unsigned long long b,
                                                   unsigned long long c) {
    unsigned long long d;
    asm("fma.rn.f32x2 %0, %1, %2, %3;" : "=l"(d) : "l"(a), "l"(b), "l"(c));
    return d;
}
__device__ __forceinline__ float upk_sum(unsigned long long v) {
    unsigned int a, b;
    asm("mov.b64 {%0, %1}, %2;" : "=r"(a), "=r"(b) : "l"(v));
    return __uint_as_float(a) + __uint_as_float(b);
}
__device__ __forceinline__ void upk(unsigned long long v, float& a, float& b) {
    unsigned int x, y;
    asm("mov.b64 {%0, %1}, %2;" : "=r"(x), "=r"(y) : "l"(v));
    a = __uint_as_float(x); b = __uint_as_float(y);
}
__device__ __forceinline__ float tanh_fast(float x) {
    float r;
    asm("tanh.approx.f32 %0, %1;" : "=f"(r) : "f"(x));
    return r;
}
__device__ __forceinline__ float sigmoid_fast(float x) {
    return fmaf(0.5f, tanh_fast(0.5f * x), 0.5f);
}
__device__ __forceinline__ float dot4(float4 a, float4 b) {
    float r = a.x * b.x;
    r = fmaf(a.y, b.y, r);
    r = fmaf(a.z, b.z, r);
    r = fmaf(a.w, b.w, r);
    return r;
}

// ---------------- kernel 1: init hidden + zero counters --------------------
__global__ __launch_bounds__(256)
void init_kernel(const float* __restrict__ nf, const float* __restrict__ Wi,
                 const float* __restrict__ bi) {
    __shared__ float Wsh[FN * HH];
    int tid = threadIdx.x;
    int gid = blockIdx.x * 256 + tid;
    if (gid < NPAD) g_count[gid] = 0;

    int j  = tid & 15;
    int nl = tid >> 4;
    int n  = blockIdx.x * 16 + nl;
    for (int idx = tid; idx < FN * HH; idx += 256) Wsh[idx] = Wi[idx];
    __syncthreads();
    if (n >= NPAD) return;
    int nr = (n < NN) ? n : (NN - 1);
    const float* row = nf + (long)nr * FN;
    float acc = bi[j];
#pragma unroll
    for (int f = 0; f < FN; f++) acc = fmaf(row[f], Wsh[f * 16 + j], acc);
    g_hidden [n * 16 + j] = acc;
    g_hidden0[n * 16 + j] = acc;
}

// ---------------- CSR build: histogram, scan, scatter ----------------------
// 2 edges per thread for atomic MLP.
__global__ __launch_bounds__(256)
void hist_kernel(const int* __restrict__ send) {
    int base = (blockIdx.x * 256 + threadIdx.x) * 2;
    int s0 = (base < EE)     ? send[base]     : -1;
    int s1 = (base + 1 < EE) ? send[base + 1] : -1;
    if (s0 >= 0) atomicAdd(&g_count[s0], 1);
    if (s1 >= 0) atomicAdd(&g_count[s1], 1);
}

__global__ __launch_bounds__(1024)
void scan_kernel() {
    __shared__ int sh[1024];
    int t = threadIdx.x;
    int vals[25];
    int sum = 0;
    int base = t * 25;
#pragma unroll
    for (int k = 0; k < 25; k++) {
        int idx = base + k;
        int v = (idx < NPAD) ? g_count[idx] : 0;
        vals[k] = v; sum += v;
    }
    sh[t] = sum;
    __syncthreads();
    for (int off = 1; off < 1024; off <<= 1) {
        int v = (t >= off) ? sh[t - off] : 0;
        __syncthreads();
        sh[t] += v;
        __syncthreads();
    }
    int ex = (t == 0) ? 0 : sh[t - 1];
#pragma unroll
    for (int k = 0; k < 25; k++) {
        int idx = base + k;
        if (idx < NPAD) { g_cursor[idx] = ex; ex += vals[k]; }
    }
}

__global__ __launch_bounds__(256)
void scatter_kernel(const int* __restrict__ send, const int* __restrict__ recv) {
    int base = (blockIdx.x * 256 + threadIdx.x) * 2;
#pragma unroll
    for (int u = 0; u < 2; u++) {
        int e = base + u;
        if (e < EE) {
            int s = send[e];
            int r = recv[e];
            int p = atomicAdd(&g_cursor[s], 1);
            g_perm[p]  = e;
            g_sends[p] = s;
            g_recvs[p] = r;
        }
    }
}

// ---------------- kernel 2: per-node T / bb  (+ zero msg fused) ------------
__global__ __launch_bounds__(256)
void t_kernel(const float* __restrict__ We, const float* __restrict__ be) {
    for (int idx = blockIdx.x * 256 + threadIdx.x; idx < NPAD * MM;
         idx += gridDim.x * 256)
        g_msg[idx] = 0.f;

    __shared__ __align__(16) float sh[64 * HH];
    int tid = threadIdx.x;
    int f = tid >> 4;
    int m = tid & 15;

    const float4* wp = (const float4*)(We + (f * 256 + m * 16));
    float4 w0 = wp[0], w1 = wp[1], w2 = wp[2], w3 = wp[3];

    float4 b0 = make_float4(0, 0, 0, 0), b1 = b0, b2 = b0, b3 = b0;
    if (f == 0) {
        const float4* bp = (const float4*)(be + m * 16);
        b0 = bp[0]; b1 = bp[1]; b2 = bp[2]; b3 = bp[3];
    }

    int base = blockIdx.x * 64;
    int cnt = NN - base;
    if (cnt > 64) cnt = 64;
    if (cnt <= 0) return;

    for (int idx = tid; idx < cnt * HH; idx += 256)
        sh[idx] = g_hidden[base * HH + idx];
    __syncthreads();

#pragma unroll 2
    for (int nl = 0; nl < cnt; nl++) {
        const float4* hp = (const float4*)(sh + nl * HH);
        float4 h0 = hp[0], h1 = hp[1], h2 = hp[2], h3 = hp[3];
        float acc = dot4(w0, h0) + dot4(w1, h1) + dot4(w2, h2) + dot4(w3, h3);
        g_T[(long)(base + nl) * 256 + tid] = acc;
        if (f == 0) {
            float bacc = dot4(b0, h0) + dot4(b1, h1) + dot4(b2, h2) + dot4(b3, h3);
            g_bb[(base + nl) * 16 + m] = bacc;
        }
    }
}

// ---------------- kernel 3: per-edge message (sorted) + vector red ---------
// 4 threads per sorted edge; mg owns m = mg*4..mg*4+3. T rows hit L1 because
// consecutive sorted edges share senders. ef accessed via perm (L2-resident).
__global__ __launch_bounds__(256)
void edge_kernel(const float* __restrict__ ef) {
    int tid = threadIdx.x;
    int i  = blockIdx.x * 64 + (tid >> 2);
    int mg = tid & 3;

    int s = g_sends[i];
    int e = g_perm[i];
    const float4* ep = (const float4*)(ef + (long)e * 16);
    float4 e0 = ep[0];
    float4 e1 = ep[1];
    float4 e2 = ep[2];
    float4 e3 = ep[3];

    float4 bbv = *(const float4*)(g_bb + s * 16 + mg * 4);
    unsigned long long accL = pk2(bbv.x, bbv.y);
    unsigned long long accH = pk2(bbv.z, bbv.w);

    const ulonglong2* Tb = (const ulonglong2*)(g_T + (long)s * 256) + mg;

#define ESTEP(F, W) { ulonglong2 tv = Tb[(F) * 4];                  \
        unsigned long long ww = pk2((W), (W));                      \
        accL = fma2(tv.x, ww, accL); accH = fma2(tv.y, ww, accH); }
    ESTEP(0,  e0.x) ESTEP(1,  e0.y) ESTEP(2,  e0.z) ESTEP(3,  e0.w)
    ESTEP(4,  e1.x) ESTEP(5,  e1.y) ESTEP(6,  e1.z) ESTEP(7,  e1.w)
    ESTEP(8,  e2.x) ESTEP(9,  e2.y) ESTEP(10, e2.z) ESTEP(11, e2.w)
    ESTEP(12, e3.x) ESTEP(13, e3.y) ESTEP(14, e3.z) ESTEP(15, e3.w)
#undef ESTEP

    float r0, r1, r2, r3;
    upk(accL, r0, r1);
    upk(accH, r2, r3);
    float* dst = g_msg + g_recvs[i] * 16 + mg * 4;
    asm volatile("red.global.add.v4.f32 [%0], {%1, %2, %3, %4};"
                 :: "l"(dst), "f"(r0), "f"(r1), "f"(r2), "f"(r3) : "memory");
}

// ---------------- kernel 4: GRU, 2 nodes per thread (ILP) ------------------
__global__ __launch_bounds__(256)
void gru_kernel(const float* __restrict__ Wi, const float* __restrict__ Wh,
                const float* __restrict__ bi, const float* __restrict__ bh) {
    __shared__ __align__(16) float sh_h[2][32][16];
    __shared__ float sh_seq[32][32];

    int tid = threadIdx.x;
    int j  = tid & 15;
    int sl = tid >> 4;                 // 0..15
    int nA = blockIdx.x * 32 + sl;
    int nB = nA + 16;

    unsigned long long wz[8], wr[8], wh[8];
#pragma unroll
    for (int k = 0; k < 8; k++) {
        wz[k] = pk2(Wh[(2 * k) * 48 + j],      Wh[(2 * k + 1) * 48 + j]);
        wr[k] = pk2(Wh[(2 * k) * 48 + 16 + j], Wh[(2 * k + 1) * 48 + 16 + j]);
        wh[k] = pk2(Wh[(2 * k) * 48 + 32 + j], Wh[(2 * k + 1) * 48 + 32 + j]);
    }
    float wiz = Wi[j], wir = Wi[16 + j], wih = Wi[32 + j];
    float biz = bi[j], bir = bi[16 + j], bih = bi[32 + j];
    float bhz = bh[j], bhr = bh[16 + j], bhh = bh[32 + j];

    sh_seq[sl][j]           = g_hidden[nA * 16 + j];
    sh_seq[sl][16 + j]      = g_msg   [nA * 16 + j];
    sh_seq[sl + 16][j]      = g_hidden[nB * 16 + j];
    sh_seq[sl + 16][16 + j] = g_msg   [nB * 16 + j];
    sh_h[0][sl][j] = 0.f;
    sh_h[0][sl + 16][j] = 0.f;
    float hA = 0.f, hB = 0.f;
    __syncthreads();

#pragma unroll 1
    for (int t = 0; t < 32; t++) {
        int cur = t & 1;
        float xA = sh_seq[sl][t];
        float xB = sh_seq[sl + 16][t];
        const ulonglong2* hpA = (const ulonglong2*)sh_h[cur][sl];
        const ulonglong2* hpB = (const ulonglong2*)sh_h[cur][sl + 16];
        unsigned long long azA = pk2(bhz, 0.f), arA = pk2(bhr, 0.f), ahA = pk2(bhh, 0.f);
        unsigned long long azB = pk2(bhz, 0.f), arB = pk2(bhr, 0.f), ahB = pk2(bhh, 0.f);
#pragma unroll
        for (int k = 0; k < 4; k++) {
            ulonglong2 pA = hpA[k];
            ulonglong2 pB = hpB[k];
            azA = fma2(pA.x, wz[2 * k],     azA);
            azA = fma2(pA.y, wz[2 * k + 1], azA);
            arA = fma2(pA.x, wr[2 * k],     arA);
            arA = fma2(pA.y, wr[2 * k + 1], arA);
            ahA = fma2(pA.x, wh[2 * k],     ahA);
            ahA = fma2(pA.y, wh[2 * k + 1], ahA);
            azB = fma2(pB.x, wz[2 * k],     azB);
            azB = fma2(pB.y, wz[2 * k + 1], azB);
            arB = fma2(pB.x, wr[2 * k],     arB);
            arB = fma2(pB.y, wr[2 * k + 1], arB);
            ahB = fma2(pB.x, wh[2 * k],     ahB);
            ahB = fma2(pB.y, wh[2 * k + 1], ahB);
        }
        {
            float ghz = upk_sum(azA), ghr = upk_sum(arA), ghh = upk_sum(ahA);
            float z = sigmoid_fast(fmaf(xA, wiz, biz) + ghz);
            float r = sigmoid_fast(fmaf(xA, wir, bir) + ghr);
            float hc = tanh_fast(fmaf(xA, wih, bih) + r * ghh);
            hA = hc + z * (hA - hc);
        }
        {
            float ghz = upk_sum(azB), ghr = upk_sum(arB), ghh = upk_sum(ahB);
            float z = sigmoid_fast(fmaf(xB, wiz, biz) + ghz);
            float r = sigmoid_fast(fmaf(xB, wir, bir) + ghr);
            float hc = tanh_fast(fmaf(xB, wih, bih) + r * ghh);
            hB = hc + z * (hB - hc);
        }
        sh_h[cur ^ 1][sl][j] = hA;
        sh_h[cur ^ 1][sl + 16][j] = hB;
        __syncwarp();
    }
    g_hidden[nA * 16 + j] = hA;
    g_hidden[nB * 16 + j] = hB;
}

// ---------------- readout --------------------------------------------------
__global__ void zero_out_kernel(float* out) { out[0] = 0.f; }

__global__ __launch_bounds__(256)
void readout_kernel(const float* __restrict__ Wri, const float* __restrict__ bri,
                    const float* __restrict__ Wrj, const float* __restrict__ brj,
                    float* __restrict__ out) {
    int n = blockIdx.x * 256 + threadIdx.x;
    float p = 0.f;
    if (n < NN) {
        const float4* hp  = (const float4*)(g_hidden  + n * 16);
        const float4* h0p = (const float4*)(g_hidden0 + n * 16);
        const float4* wi  = (const float4*)Wri;
        const float4* wj  = (const float4*)Wrj;
        float4 h0 = hp[0], h1 = hp[1], h2 = hp[2], h3 = hp[3];
        float4 g0 = h0p[0], g1 = h0p[1], g2 = h0p[2], g3 = h0p[3];
        float iv = bri[0]
                 + dot4(h0, wi[0]) + dot4(h1, wi[1]) + dot4(h2, wi[2]) + dot4(h3, wi[3])
                 + dot4(g0, wi[4]) + dot4(g1, wi[5]) + dot4(g2, wi[6]) + dot4(g3, wi[7]);
        float jv = brj[0]
                 + dot4(h0, wj[0]) + dot4(h1, wj[1]) + dot4(h2, wj[2]) + dot4(h3, wj[3]);
        p = iv * jv;
    }
#pragma unroll
    for (int off = 16; off > 0; off >>= 1)
        p += __shfl_down_sync(0xffffffffu, p, off);
    if ((threadIdx.x & 31) == 0) atomicAdd(out, p);
}

// ---------------- launch ---------------------------------------------------
extern "C" void kernel_launch(void* const* d_in, const int* in_sizes, int n_in,
                              void* d_out, int out_size) {
    const float* nf     = (const float*)d_in[0];
    const float* ef     = (const float*)d_in[1];
    const float* W_init = (const float*)d_in[2];
    const float* b_init = (const float*)d_in[3];
    const float* W_edge = (const float*)d_in[4];
    const float* b_edge = (const float*)d_in[5];
    const float* Wi_gru = (const float*)d_in[6];
    const float* Wh_gru = (const float*)d_in[7];
    const float* bi_gru = (const float*)d_in[8];
    const float* bh_gru = (const float*)d_in[9];
    const float* W_ri   = (const float*)d_in[10];
    const float* b_ri   = (const float*)d_in[11];
    const float* W_rj   = (const float*)d_in[12];
    const float* b_rj   = (const float*)d_in[13];
    const int*   recv   = (const int*)d_in[14];
    const int*   send   = (const int*)d_in[15];
    float* out = (float*)d_out;

    init_kernel<<<NPAD / 16, 256>>>(nf, W_init, b_init);
    hist_kernel<<<(EE / 2 + 255) / 256, 256>>>(send);
    scan_kernel<<<1, 1024>>>();
    scatter_kernel<<<(EE / 2 + 255) / 256, 256>>>(send, recv);

    for (int it = 0; it < MPITERS; it++) {
        t_kernel<<<(NN + 63) / 64, 256>>>(W_edge, b_edge);
        edge_kernel<<<EE / 64, 256>>>(ef);
        gru_kernel<<<NPAD / 32, 256>>>(Wi_gru, Wh_gru, bi_gru, bh_gru);
    }

    zero_out_kernel<<<1, 1>>>(out);
    readout_kernel<<<(NN + 255) / 256, 256>>>(W_ri, b_ri, W_rj, b_rj, out);
}

// round 4
// speedup vs baseline: 1.3780x; 1.0388x over previous
#include <cuda_runtime.h>

// Problem constants
#define NN    25000
#define NPAD  25024          // multiple of 64
#define EE    400000
#define FN    32
#define FE    16
#define HH    16
#define MM    16
#define MPITERS 3

// ---------------- scratch (device globals) ---------------------------------
__device__ float g_hidden [NPAD * HH];
__device__ float g_hidden0[NPAD * HH];
__device__ float g_T      [NPAD * FE * MM];   // T[n][f*16+m]
__device__ float g_bb     [NPAD * MM];
__device__ float g_msg    [NPAD * MM];
__device__ int   g_count  [NPAD];
__device__ int   g_cursor [NPAD];
__device__ int   g_perm   [EE];
__device__ int   g_recvs  [EE];
__device__ int   g_sends  [EE];

// ---------------- f32x2 helpers -------------------------------------------
__device__ __forceinline__ unsigned long long pk2(float lo, float hi) {
    unsigned long long d;
    asm("mov.b64 %0, {%1, %2};" : "=l"(d) : "r"(__float_as_uint(lo)), "r"(__float_as_uint(hi)));
    return d;
}
__device__ __forceinline__ unsigned long long fma2(unsigned long long a,
                                                   unsigned long long b,
                                                   unsigned long long c) {
    unsigned long long d;
    asm("fma.rn.f32x2 %0, %1, %2, %3;" : "=l"(d) : "l"(a), "l"(b), "l"(c));
    return d;
}
__device__ __forceinline__ float upk_sum(unsigned long long v) {
    unsigned int a, b;
    asm("mov.b64 {%0, %1}, %2;" : "=r"(a), "=r"(b) : "l"(v));
    return __uint_as_float(a) + __uint_as_float(b);
}
__device__ __forceinline__ void upk(unsigned long long v, float& a, float& b) {
    unsigned int x, y;
    asm("mov.b64 {%0, %1}, %2;" : "=r"(x), "=r"(y) : "l"(v));
    a = __uint_as_float(x); b = __uint_as_float(y);
}
__device__ __forceinline__ float tanh_fast(float x) {
    float r;
    asm("tanh.approx.f32 %0, %1;" : "=f"(r) : "f"(x));
    return r;
}
__device__ __forceinline__ float sigmoid_fast(float x) {
    return fmaf(0.5f, tanh_fast(0.5f * x), 0.5f);
}
__device__ __forceinline__ float dot4(float4 a, float4 b) {
    float r = a.x * b.x;
    r = fmaf(a.y, b.y, r);
    r = fmaf(a.z, b.z, r);
    r = fmaf(a.w, b.w, r);
    return r;
}

// ---------------- kernel 1: init hidden + zero counters + zero out ---------
__global__ __launch_bounds__(256)
void init_kernel(const float* __restrict__ nf, const float* __restrict__ Wi,
                 const float* __restrict__ bi, float* __restrict__ out) {
    __shared__ float Wsh[FN * HH];
    int tid = threadIdx.x;
    int gid = blockIdx.x * 256 + tid;
    if (gid < NPAD) g_count[gid] = 0;
    if (gid == 0) out[0] = 0.f;

    int j  = tid & 15;
    int nl = tid >> 4;
    int n  = blockIdx.x * 16 + nl;
    for (int idx = tid; idx < FN * HH; idx += 256) Wsh[idx] = Wi[idx];
    __syncthreads();
    if (n >= NPAD) return;
    int nr = (n < NN) ? n : (NN - 1);
    const float* row = nf + (long)nr * FN;
    float acc = bi[j];
#pragma unroll
    for (int f = 0; f < FN; f++) acc = fmaf(row[f], Wsh[f * 16 + j], acc);
    g_hidden [n * 16 + j] = acc;
    g_hidden0[n * 16 + j] = acc;
}

// ---------------- CSR build ------------------------------------------------
__global__ __launch_bounds__(256)
void hist_kernel(const int* __restrict__ send) {
    int e = blockIdx.x * 256 + threadIdx.x;
    if (e < EE) atomicAdd(&g_count[send[e]], 1);
}

__global__ __launch_bounds__(1024)
void scan_kernel() {
    __shared__ int sh[1024];
    int t = threadIdx.x;
    int vals[25];
    int sum = 0;
    int base = t * 25;
#pragma unroll
    for (int k = 0; k < 25; k++) {
        int idx = base + k;
        int v = (idx < NPAD) ? g_count[idx] : 0;
        vals[k] = v; sum += v;
    }
    sh[t] = sum;
    __syncthreads();
    for (int off = 1; off < 1024; off <<= 1) {
        int v = (t >= off) ? sh[t - off] : 0;
        __syncthreads();
        sh[t] += v;
        __syncthreads();
    }
    int ex = (t == 0) ? 0 : sh[t - 1];
#pragma unroll
    for (int k = 0; k < 25; k++) {
        int idx = base + k;
        if (idx < NPAD) { g_cursor[idx] = ex; ex += vals[k]; }
    }
}

__global__ __launch_bounds__(256)
void scatter_kernel(const int* __restrict__ send, const int* __restrict__ recv) {
    int e = blockIdx.x * 256 + threadIdx.x;
    if (e < EE) {
        int s = send[e];
        int r = recv[e];
        int p = atomicAdd(&g_cursor[s], 1);
        g_perm[p]  = e;
        g_sends[p] = s;
        g_recvs[p] = r;
    }
}

// ---------------- kernel 2: per-node T / bb (+ zero msg fused) -------------
__global__ __launch_bounds__(256)
void t_kernel(const float* __restrict__ We, const float* __restrict__ be) {
    for (int idx = blockIdx.x * 256 + threadIdx.x; idx < NPAD * MM;
         idx += gridDim.x * 256)
        g_msg[idx] = 0.f;

    __shared__ __align__(16) float sh[64 * HH];
    int tid = threadIdx.x;
    int f = tid >> 4;
    int m = tid & 15;

    const float4* wp = (const float4*)(We + (f * 256 + m * 16));
    float4 w0 = wp[0], w1 = wp[1], w2 = wp[2], w3 = wp[3];

    float4 b0 = make_float4(0, 0, 0, 0), b1 = b0, b2 = b0, b3 = b0;
    if (f == 0) {
        const float4* bp = (const float4*)(be + m * 16);
        b0 = bp[0]; b1 = bp[1]; b2 = bp[2]; b3 = bp[3];
    }

    int base = blockIdx.x * 64;
    int cnt = NN - base;
    if (cnt > 64) cnt = 64;
    if (cnt <= 0) return;

    for (int idx = tid; idx < cnt * HH; idx += 256)
        sh[idx] = g_hidden[base * HH + idx];
    __syncthreads();

#pragma unroll 2
    for (int nl = 0; nl < cnt; nl++) {
        const float4* hp = (const float4*)(sh + nl * HH);
        float4 h0 = hp[0], h1 = hp[1], h2 = hp[2], h3 = hp[3];
        float acc = dot4(w0, h0) + dot4(w1, h1) + dot4(w2, h2) + dot4(w3, h3);
        g_T[(long)(base + nl) * 256 + tid] = acc;
        if (f == 0) {
            float bacc = dot4(b0, h0) + dot4(b1, h1) + dot4(b2, h2) + dot4(b3, h3);
            g_bb[(base + nl) * 16 + m] = bacc;
        }
    }
}

// ---------------- kernel 3: per-edge message, batched loads ----------------
// 4 threads/edge (mg = m-quad). All 16 T loads issued into a register array
// BEFORE the fma chain -> MLP ~16, hides L1/L2 latency.
__global__ __launch_bounds__(256)
void edge_kernel(const float* __restrict__ ef) {
    int tid = threadIdx.x;
    int i  = blockIdx.x * 64 + (tid >> 2);
    int mg = tid & 3;

    int s = g_sends[i];
    int e = g_perm[i];
    int r = g_recvs[i];

    const float4* ep = (const float4*)(ef + (long)e * 16);
    float4 e0 = ep[0];
    float4 e1 = ep[1];
    float4 e2 = ep[2];
    float4 e3 = ep[3];

    const ulonglong2* Tb = (const ulonglong2*)(g_T + (long)s * 256) + mg;
    ulonglong2 tv[16];
#pragma unroll
    for (int F = 0; F < 16; F++) tv[F] = Tb[F * 4];

    float4 bbv = *(const float4*)(g_bb + s * 16 + mg * 4);
    unsigned long long accL = pk2(bbv.x, bbv.y);
    unsigned long long accH = pk2(bbv.z, bbv.w);

    float w[16] = {e0.x, e0.y, e0.z, e0.w, e1.x, e1.y, e1.z, e1.w,
                   e2.x, e2.y, e2.z, e2.w, e3.x, e3.y, e3.z, e3.w};
#pragma unroll
    for (int F = 0; F < 16; F++) {
        unsigned long long ww = pk2(w[F], w[F]);
        accL = fma2(tv[F].x, ww, accL);
        accH = fma2(tv[F].y, ww, accH);
    }

    float r0, r1, r2, r3;
    upk(accL, r0, r1);
    upk(accH, r2, r3);
    float* dst = g_msg + r * 16 + mg * 4;
    asm volatile("red.global.add.v4.f32 [%0], {%1, %2, %3, %4};"
                 :: "l"(dst), "f"(r0), "f"(r1), "f"(r2), "f"(r3) : "memory");
}

// ---------------- kernel 4: GRU, 4 nodes per thread ------------------------
__global__ __launch_bounds__(256)
void gru_kernel(const float* __restrict__ Wi, const float* __restrict__ Wh,
                const float* __restrict__ bi, const float* __restrict__ bh) {
    __shared__ __align__(16) float sh_h[2][64][16];
    __shared__ float sh_seq[64][33];

    int tid = threadIdx.x;
    int j  = tid & 15;
    int sl = tid >> 4;                 // 0..15
    int nbase = blockIdx.x * 64;

    unsigned long long wz[8], wr[8], wh[8];
#pragma unroll
    for (int k = 0; k < 8; k++) {
        wz[k] = pk2(Wh[(2 * k) * 48 + j],      Wh[(2 * k + 1) * 48 + j]);
        wr[k] = pk2(Wh[(2 * k) * 48 + 16 + j], Wh[(2 * k + 1) * 48 + 16 + j]);
        wh[k] = pk2(Wh[(2 * k) * 48 + 32 + j], Wh[(2 * k + 1) * 48 + 32 + j]);
    }
    float wiz = Wi[j], wir = Wi[16 + j], wih = Wi[32 + j];
    float biz = bi[j], bir = bi[16 + j], bih = bi[32 + j];
    float bhz = bh[j], bhr = bh[16 + j], bhh = bh[32 + j];

    float h[4];
#pragma unroll
    for (int u = 0; u < 4; u++) {
        int row = sl + u * 16;
        int n = nbase + row;
        sh_seq[row][j]      = g_hidden[n * 16 + j];
        sh_seq[row][16 + j] = g_msg   [n * 16 + j];
        sh_h[0][row][j] = 0.f;
        h[u] = 0.f;
    }
    __syncthreads();

#pragma unroll 1
    for (int t = 0; t < 32; t++) {
        int cur = t & 1;
        float x[4];
        unsigned long long az[4], ar[4], ah[4];
#pragma unroll
        for (int u = 0; u < 4; u++) {
            x[u] = sh_seq[sl + u * 16][t];
            az[u] = pk2(bhz, 0.f);
            ar[u] = pk2(bhr, 0.f);
            ah[u] = pk2(bhh, 0.f);
        }
#pragma unroll
        for (int k = 0; k < 4; k++) {
#pragma unroll
            for (int u = 0; u < 4; u++) {
                ulonglong2 p = ((const ulonglong2*)sh_h[cur][sl + u * 16])[k];
                az[u] = fma2(p.x, wz[2 * k],     az[u]);
                az[u] = fma2(p.y, wz[2 * k + 1], az[u]);
                ar[u] = fma2(p.x, wr[2 * k],     ar[u]);
                ar[u] = fma2(p.y, wr[2 * k + 1], ar[u]);
                ah[u] = fma2(p.x, wh[2 * k],     ah[u]);
                ah[u] = fma2(p.y, wh[2 * k + 1], ah[u]);
            }
        }
#pragma unroll
        for (int u = 0; u < 4; u++) {
            float ghz = upk_sum(az[u]), ghr = upk_sum(ar[u]), ghh = upk_sum(ah[u]);
            float z = sigmoid_fast(fmaf(x[u], wiz, biz) + ghz);
            float r = sigmoid_fast(fmaf(x[u], wir, bir) + ghr);
            float hc = tanh_fast(fmaf(x[u], wih, bih) + r * ghh);
            h[u] = hc + z * (h[u] - hc);
            sh_h[cur ^ 1][sl + u * 16][j] = h[u];
        }
        __syncwarp();
    }
#pragma unroll
    for (int u = 0; u < 4; u++)
        g_hidden[(nbase + sl + u * 16) * 16 + j] = h[u];
}

// ---------------- readout --------------------------------------------------
__global__ __launch_bounds__(256)
void readout_kernel(const float* __restrict__ Wri, const float* __restrict__ bri,
                    const float* __restrict__ Wrj, const float* __restrict__ brj,
                    float* __restrict__ out) {
    int n = blockIdx.x * 256 + threadIdx.x;
    float p = 0.f;
    if (n < NN) {
        const float4* hp  = (const float4*)(g_hidden  + n * 16);
        const float4* h0p = (const float4*)(g_hidden0 + n * 16);
        const float4* wi  = (const float4*)Wri;
        const float4* wj  = (const float4*)Wrj;
        float4 h0 = hp[0], h1 = hp[1], h2 = hp[2], h3 = hp[3];
        float4 g0 = h0p[0], g1 = h0p[1], g2 = h0p[2], g3 = h0p[3];
        float iv = bri[0]
                 + dot4(h0, wi[0]) + dot4(h1, wi[1]) + dot4(h2, wi[2]) + dot4(h3, wi[3])
                 + dot4(g0, wi[4]) + dot4(g1, wi[5]) + dot4(g2, wi[6]) + dot4(g3, wi[7]);
        float jv = brj[0]
                 + dot4(h0, wj[0]) + dot4(h1, wj[1]) + dot4(h2, wj[2]) + dot4(h3, wj[3]);
        p = iv * jv;
    }
#pragma unroll
    for (int off = 16; off > 0; off >>= 1)
        p += __shfl_down_sync(0xffffffffu, p, off);
    if ((threadIdx.x & 31) == 0) atomicAdd(out, p);
}

// ---------------- launch ---------------------------------------------------
extern "C" void kernel_launch(void* const* d_in, const int* in_sizes, int n_in,
                              void* d_out, int out_size) {
    const float* nf     = (const float*)d_in[0];
    const float* ef     = (const float*)d_in[1];
    const float* W_init = (const float*)d_in[2];
    const float* b_init = (const float*)d_in[3];
    const float* W_edge = (const float*)d_in[4];
    const float* b_edge = (const float*)d_in[5];
    const float* Wi_gru = (const float*)d_in[6];
    const float* Wh_gru = (const float*)d_in[7];
    const float* bi_gru = (const float*)d_in[8];
    const float* bh_gru = (const float*)d_in[9];
    const float* W_ri   = (const float*)d_in[10];
    const float* b_ri   = (const float*)d_in[11];
    const float* W_rj   = (const float*)d_in[12];
    const float* b_rj   = (const float*)d_in[13];
    const int*   recv   = (const int*)d_in[14];
    const int*   send   = (const int*)d_in[15];
    float* out = (float*)d_out;

    init_kernel<<<(NPAD + 255) / 256 * 16, 256>>>(nf, W_init, b_init, out);
    hist_kernel<<<(EE + 255) / 256, 256>>>(send);
    scan_kernel<<<1, 1024>>>();
    scatter_kernel<<<(EE + 255) / 256, 256>>>(send, recv);

    for (int it = 0; it < MPITERS; it++) {
        t_kernel<<<(NN + 63) / 64, 256>>>(W_edge, b_edge);
        edge_kernel<<<EE / 64, 256>>>(ef);
        gru_kernel<<<NPAD / 64, 256>>>(Wi_gru, Wh_gru, bi_gru, bh_gru);
    }

    readout_kernel<<<(NN + 255) / 256, 256>>>(W_ri, b_ri, W_rj, b_rj, out);
}